// round 1
// baseline (speedup 1.0000x reference)
#include <cuda_runtime.h>
#include <math.h>

#define BB 8
#define NN 4096
#define DD 512
// 1 / 512^(1/4)
#define ESCALE 0.2102241038134287f

// ---------------- scratch (device globals; no allocs allowed) ----------------
__device__ float g_Qe[BB * NN * DD];   // exp(Q / s)        64 MB
__device__ float g_Ke[BB * NN * DD];   // exp(K / s)        64 MB
__device__ float g_V [BB * NN * DD];   // V                 64 MB
__device__ float g_Bm[BB * DD * DD];   // Bm'' (scaled)      8 MB
__device__ float g_partQ[BB * 8 * DD];
__device__ float g_partK[BB * 8 * DD];
__device__ float g_nrm[BB * DD];       // 1/(Lq*Lk)

// ---------------- packed f32x2 helpers (Blackwell dual-rate FMA) -------------
#define PK2(d, s) asm("mov.b64 %0, {%1, %1};" : "=l"(d) : "r"(__float_as_uint(s)))
#define FMA2(c, a, b2) asm("fma.rn.f32x2 %0, %1, %2, %0;" : "+l"(c) : "l"(a), "l"(b2))

// ---------------- generic 128x128x8 fp32 GEMM ----------------
// TRANSA = 0: A is [M,K] row-major (lda=K)
// TRANSA = 1: A is stored [K,M] (lda=M)  (used for Ke^T @ V)
// EPI: 0 = +bias ; 1 = exp((acc+bias)*ESCALE) ; 2 = acc * nrm[b*DD+m] ; 3 = plain
template <int TRANSA, int EPI>
__global__ __launch_bounds__(256)
void gemm128(const float* __restrict__ A, const float* __restrict__ Bg,
             const float* __restrict__ aux, float* __restrict__ C,
             int M, int Nn, int K, long sA, long sB, long sC)
{
    __shared__ float As[8][128];
    __shared__ float Bs[8][128];

    const int b   = blockIdx.z;
    const int m0  = blockIdx.y * 128;
    const int n0  = blockIdx.x * 128;
    const int tid = threadIdx.x;
    const int tx  = tid & 15;
    const int ty  = tid >> 4;

    const float* Ab = A + (long)b * sA;
    const float* Bb = Bg + (long)b * sB;
    float*       Cb = C + (long)b * sC;

    // B tile: row kb (0..7), col nb (0..124 step4). Same layout for TRANSA=1 A tile.
    const int kb = tid >> 5;
    const int nb = (tid & 31) * 4;
    // A tile (TRANSA=0): row ar (0..127), cols ac..ac+3
    const int ar = tid >> 1;
    const int ac = (tid & 1) * 4;

    unsigned long long acc[8][4];
    #pragma unroll
    for (int i = 0; i < 8; i++)
        #pragma unroll
        for (int j = 0; j < 4; j++) acc[i][j] = 0ull;

    const int ntiles = K >> 3;

    float4 aL, bL;
    if (TRANSA == 0)
        aL = *(const float4*)(Ab + (long)(m0 + ar) * K + ac);
    else
        aL = *(const float4*)(Ab + (long)kb * M + m0 + nb);
    bL = *(const float4*)(Bb + (long)kb * Nn + n0 + nb);

    for (int kt = 0; kt < ntiles; kt++) {
        __syncthreads();
        if (TRANSA == 0) {
            As[ac + 0][ar] = aL.x;
            As[ac + 1][ar] = aL.y;
            As[ac + 2][ar] = aL.z;
            As[ac + 3][ar] = aL.w;
        } else {
            *(float4*)&As[kb][nb] = aL;
        }
        *(float4*)&Bs[kb][nb] = bL;
        __syncthreads();

        if (kt + 1 < ntiles) {
            const int k1 = (kt + 1) << 3;
            if (TRANSA == 0)
                aL = *(const float4*)(Ab + (long)(m0 + ar) * K + k1 + ac);
            else
                aL = *(const float4*)(Ab + (long)(k1 + kb) * M + m0 + nb);
            bL = *(const float4*)(Bb + (long)(k1 + kb) * Nn + n0 + nb);
        }

        #pragma unroll
        for (int k = 0; k < 8; k++) {
            const float4 a0 = *(const float4*)&As[k][ty * 8];
            const float4 a1 = *(const float4*)&As[k][ty * 8 + 4];
            const ulonglong2 b0 = *(const ulonglong2*)&Bs[k][tx * 8];
            const ulonglong2 b1 = *(const ulonglong2*)&Bs[k][tx * 8 + 4];
            unsigned long long ap[8];
            PK2(ap[0], a0.x); PK2(ap[1], a0.y); PK2(ap[2], a0.z); PK2(ap[3], a0.w);
            PK2(ap[4], a1.x); PK2(ap[5], a1.y); PK2(ap[6], a1.z); PK2(ap[7], a1.w);
            const unsigned long long bp0 = b0.x, bp1 = b0.y, bp2 = b1.x, bp3 = b1.y;
            #pragma unroll
            for (int i = 0; i < 8; i++) {
                FMA2(acc[i][0], ap[i], bp0);
                FMA2(acc[i][1], ap[i], bp1);
                FMA2(acc[i][2], ap[i], bp2);
                FMA2(acc[i][3], ap[i], bp3);
            }
        }
    }

    // epilogue
    #pragma unroll
    for (int i = 0; i < 8; i++) {
        const int m = m0 + ty * 8 + i;
        const int n = n0 + tx * 8;
        float v[8];
        #pragma unroll
        for (int j = 0; j < 4; j++) {
            v[2 * j]     = __uint_as_float((unsigned)(acc[i][j] & 0xffffffffull));
            v[2 * j + 1] = __uint_as_float((unsigned)(acc[i][j] >> 32));
        }
        if constexpr (EPI == 0 || EPI == 1) {
            #pragma unroll
            for (int c = 0; c < 8; c++) v[c] += aux[n + c];
        }
        if constexpr (EPI == 1) {
            #pragma unroll
            for (int c = 0; c < 8; c++) v[c] = expf(v[c] * ESCALE);
        }
        if constexpr (EPI == 2) {
            const float s = aux[b * DD + m];
            #pragma unroll
            for (int c = 0; c < 8; c++) v[c] *= s;
        }
        float* cp = Cb + (long)m * Nn + n;
        *(float4*)cp       = make_float4(v[0], v[1], v[2], v[3]);
        *(float4*)(cp + 4) = make_float4(v[4], v[5], v[6], v[7]);
    }
}

// ---------------- column sums of exp-matrices (split over n, deterministic) --
__global__ void colsum_part(const float* __restrict__ src, float* __restrict__ part)
{
    const int d  = blockIdx.x * 256 + threadIdx.x;
    const int b  = blockIdx.z;
    const int n0 = blockIdx.y * (NN / 8);
    const float* p = src + ((long)b * NN + n0) * DD + d;
    float s0 = 0.f, s1 = 0.f, s2 = 0.f, s3 = 0.f;
    for (int n = 0; n < NN / 8; n += 4) {
        s0 += p[(long)(n + 0) * DD];
        s1 += p[(long)(n + 1) * DD];
        s2 += p[(long)(n + 2) * DD];
        s3 += p[(long)(n + 3) * DD];
    }
    part[((long)b * 8 + blockIdx.y) * DD + d] = (s0 + s1) + (s2 + s3);
}

__global__ void colsum_combine()
{
    const int d = blockIdx.x * 256 + threadIdx.x;
    const int b = blockIdx.y;
    float lq = 0.f, lk = 0.f;
    #pragma unroll
    for (int c = 0; c < 8; c++) {
        lq += g_partQ[((long)b * 8 + c) * DD + d];
        lk += g_partK[((long)b * 8 + c) * DD + d];
    }
    g_nrm[b * DD + d] = 1.0f / (lq * lk);
}

// ---------------- launch ----------------
extern "C" void kernel_launch(void* const* d_in, const int* in_sizes, int n_in,
                              void* d_out, int out_size)
{
    const float* x_q = (const float*)d_in[0];
    const float* x_k = (const float*)d_in[1];
    const float* x_v = (const float*)d_in[2];
    const float* W_q = (const float*)d_in[3];
    const float* b_q = (const float*)d_in[4];
    const float* W_k = (const float*)d_in[5];
    const float* b_k = (const float*)d_in[6];
    const float* W_v = (const float*)d_in[7];
    const float* b_v = (const float*)d_in[8];
    float* out = (float*)d_out;

    float *Qe, *Ke, *V, *Bm, *pQ, *pK, *nrm;
    cudaGetSymbolAddress((void**)&Qe,  g_Qe);
    cudaGetSymbolAddress((void**)&Ke,  g_Ke);
    cudaGetSymbolAddress((void**)&V,   g_V);
    cudaGetSymbolAddress((void**)&Bm,  g_Bm);
    cudaGetSymbolAddress((void**)&pQ,  g_partQ);
    cudaGetSymbolAddress((void**)&pK,  g_partK);
    cudaGetSymbolAddress((void**)&nrm, g_nrm);

    const long sX = (long)NN * DD;   // batched activation stride
    const long sBm = (long)DD * DD;

    dim3 gProj(DD / 128, NN / 128, BB);     // (4, 32, 8)
    // Projections; Q and K write exp(val/s) directly, V raw.
    gemm128<0, 1><<<gProj, 256>>>(x_q, W_q, b_q, Qe, NN, DD, DD, sX, 0, sX);
    gemm128<0, 1><<<gProj, 256>>>(x_k, W_k, b_k, Ke, NN, DD, DD, sX, 0, sX);
    gemm128<0, 0><<<gProj, 256>>>(x_v, W_v, b_v, V,  NN, DD, DD, sX, 0, sX);

    // Column sums -> combined normalizer 1/(Lq*Lk)
    colsum_part<<<dim3(DD / 256, 8, BB), 256>>>(Qe, pQ);
    colsum_part<<<dim3(DD / 256, 8, BB), 256>>>(Ke, pK);
    colsum_combine<<<dim3(DD / 256, BB), 256>>>();

    // Bm''[d,e] = (sum_n expK[n,d] * V[n,e]) / (Lq[d]*Lk[d])
    dim3 gBm(DD / 128, DD / 128, BB);       // (4, 4, 8)
    gemm128<1, 2><<<gBm, 256>>>(Ke, V, nrm, Bm, DD, DD, NN, sX, sX, sBm);

    // Z = expQ @ Bm''
    dim3 gZ(DD / 128, NN / 128, BB);        // (4, 32, 8)
    gemm128<0, 3><<<gZ, 256>>>(Qe, Bm, nullptr, out, NN, DD, DD, sX, sBm, sX);
}

// round 2
// speedup vs baseline: 1.0013x; 1.0013x over previous
#include <cuda_runtime.h>
#include <math.h>

#define BB 8
#define NN 4096
#define DD 512
// 1 / 512^(1/4)
#define ESCALE 0.2102241038134287f

// ---------------- scratch (device globals; no allocs allowed) ----------------
__device__ float g_Qe[BB * NN * DD];   // exp(Q / s)        64 MB
__device__ float g_Ke[BB * NN * DD];   // exp(K / s)        64 MB
__device__ float g_V [BB * NN * DD];   // V                 64 MB
__device__ float g_Bm[BB * DD * DD];   // Bm'' (scaled)      8 MB
__device__ float g_partQ[BB * 8 * DD];
__device__ float g_partK[BB * 8 * DD];
__device__ float g_nrm[BB * DD];       // 1/(Lq*Lk)

// ---------------- packed f32x2 helpers (Blackwell dual-rate FMA) -------------
#define PK2(d, s) asm("mov.b64 %0, {%1, %1};" : "=l"(d) : "r"(__float_as_uint(s)))
#define FMA2(c, a, b2) asm("fma.rn.f32x2 %0, %1, %2, %0;" : "+l"(c) : "l"(a), "l"(b2))

// ---------------- generic 128x128x8 fp32 GEMM ----------------
// TRANSA = 0: A is [M,K] row-major (lda=K)
// TRANSA = 1: A is stored [K,M] (lda=M)  (used for Ke^T @ V)
// EPI: 0 = +bias ; 1 = exp((acc+bias)*ESCALE) ; 2 = acc * nrm[b*DD+m] ; 3 = plain
template <int TRANSA, int EPI>
__global__ __launch_bounds__(256)
void gemm128(const float* __restrict__ A, const float* __restrict__ Bg,
             const float* __restrict__ aux, float* __restrict__ C,
             int M, int Nn, int K, long sA, long sB, long sC)
{
    __shared__ float As[8][128];
    __shared__ float Bs[8][128];

    const int b   = blockIdx.z;
    const int m0  = blockIdx.y * 128;
    const int n0  = blockIdx.x * 128;
    const int tid = threadIdx.x;
    const int tx  = tid & 15;
    const int ty  = tid >> 4;

    const float* Ab = A + (long)b * sA;
    const float* Bb = Bg + (long)b * sB;
    float*       Cb = C + (long)b * sC;

    // B tile: row kb (0..7), col nb (0..124 step4). Same layout for TRANSA=1 A tile.
    const int kb = tid >> 5;
    const int nb = (tid & 31) * 4;
    // A tile (TRANSA=0): row ar (0..127), cols ac..ac+3
    const int ar = tid >> 1;
    const int ac = (tid & 1) * 4;

    unsigned long long acc[8][4];
    #pragma unroll
    for (int i = 0; i < 8; i++)
        #pragma unroll
        for (int j = 0; j < 4; j++) acc[i][j] = 0ull;

    const int ntiles = K >> 3;

    float4 aL, bL;
    if (TRANSA == 0)
        aL = *(const float4*)(Ab + (long)(m0 + ar) * K + ac);
    else
        aL = *(const float4*)(Ab + (long)kb * M + m0 + nb);
    bL = *(const float4*)(Bb + (long)kb * Nn + n0 + nb);

    for (int kt = 0; kt < ntiles; kt++) {
        __syncthreads();
        if (TRANSA == 0) {
            As[ac + 0][ar] = aL.x;
            As[ac + 1][ar] = aL.y;
            As[ac + 2][ar] = aL.z;
            As[ac + 3][ar] = aL.w;
        } else {
            *(float4*)&As[kb][nb] = aL;
        }
        *(float4*)&Bs[kb][nb] = bL;
        __syncthreads();

        if (kt + 1 < ntiles) {
            const int k1 = (kt + 1) << 3;
            if (TRANSA == 0)
                aL = *(const float4*)(Ab + (long)(m0 + ar) * K + k1 + ac);
            else
                aL = *(const float4*)(Ab + (long)(k1 + kb) * M + m0 + nb);
            bL = *(const float4*)(Bb + (long)(k1 + kb) * Nn + n0 + nb);
        }

        #pragma unroll
        for (int k = 0; k < 8; k++) {
            const float4 a0 = *(const float4*)&As[k][ty * 8];
            const float4 a1 = *(const float4*)&As[k][ty * 8 + 4];
            const ulonglong2 b0 = *(const ulonglong2*)&Bs[k][tx * 8];
            const ulonglong2 b1 = *(const ulonglong2*)&Bs[k][tx * 8 + 4];
            unsigned long long ap[8];
            PK2(ap[0], a0.x); PK2(ap[1], a0.y); PK2(ap[2], a0.z); PK2(ap[3], a0.w);
            PK2(ap[4], a1.x); PK2(ap[5], a1.y); PK2(ap[6], a1.z); PK2(ap[7], a1.w);
            const unsigned long long bp0 = b0.x, bp1 = b0.y, bp2 = b1.x, bp3 = b1.y;
            #pragma unroll
            for (int i = 0; i < 8; i++) {
                FMA2(acc[i][0], ap[i], bp0);
                FMA2(acc[i][1], ap[i], bp1);
                FMA2(acc[i][2], ap[i], bp2);
                FMA2(acc[i][3], ap[i], bp3);
            }
        }
    }

    // epilogue
    #pragma unroll
    for (int i = 0; i < 8; i++) {
        const int m = m0 + ty * 8 + i;
        const int n = n0 + tx * 8;
        float v[8];
        #pragma unroll
        for (int j = 0; j < 4; j++) {
            v[2 * j]     = __uint_as_float((unsigned)(acc[i][j] & 0xffffffffull));
            v[2 * j + 1] = __uint_as_float((unsigned)(acc[i][j] >> 32));
        }
        if constexpr (EPI == 0 || EPI == 1) {
            #pragma unroll
            for (int c = 0; c < 8; c++) v[c] += aux[n + c];
        }
        if constexpr (EPI == 1) {
            #pragma unroll
            for (int c = 0; c < 8; c++) v[c] = expf(v[c] * ESCALE);
        }
        if constexpr (EPI == 2) {
            const float s = aux[b * DD + m];
            #pragma unroll
            for (int c = 0; c < 8; c++) v[c] *= s;
        }
        float* cp = Cb + (long)m * Nn + n;
        *(float4*)cp       = make_float4(v[0], v[1], v[2], v[3]);
        *(float4*)(cp + 4) = make_float4(v[4], v[5], v[6], v[7]);
    }
}

// ---------------- column sums of exp-matrices (split over n, deterministic) --
__global__ void colsum_part(const float* __restrict__ src, float* __restrict__ part)
{
    const int d  = blockIdx.x * 256 + threadIdx.x;
    const int b  = blockIdx.z;
    const int n0 = blockIdx.y * (NN / 8);
    const float* p = src + ((long)b * NN + n0) * DD + d;
    float s0 = 0.f, s1 = 0.f, s2 = 0.f, s3 = 0.f;
    for (int n = 0; n < NN / 8; n += 4) {
        s0 += p[(long)(n + 0) * DD];
        s1 += p[(long)(n + 1) * DD];
        s2 += p[(long)(n + 2) * DD];
        s3 += p[(long)(n + 3) * DD];
    }
    part[((long)b * 8 + blockIdx.y) * DD + d] = (s0 + s1) + (s2 + s3);
}

__global__ void colsum_combine()
{
    const int d = blockIdx.x * 256 + threadIdx.x;
    const int b = blockIdx.y;
    float lq = 0.f, lk = 0.f;
    #pragma unroll
    for (int c = 0; c < 8; c++) {
        lq += g_partQ[((long)b * 8 + c) * DD + d];
        lk += g_partK[((long)b * 8 + c) * DD + d];
    }
    g_nrm[b * DD + d] = 1.0f / (lq * lk);
}

// ---------------- launch ----------------
extern "C" void kernel_launch(void* const* d_in, const int* in_sizes, int n_in,
                              void* d_out, int out_size)
{
    const float* x_q = (const float*)d_in[0];
    const float* x_k = (const float*)d_in[1];
    const float* x_v = (const float*)d_in[2];
    const float* W_q = (const float*)d_in[3];
    const float* b_q = (const float*)d_in[4];
    const float* W_k = (const float*)d_in[5];
    const float* b_k = (const float*)d_in[6];
    const float* W_v = (const float*)d_in[7];
    const float* b_v = (const float*)d_in[8];
    float* out = (float*)d_out;

    float *Qe, *Ke, *V, *Bm, *pQ, *pK, *nrm;
    cudaGetSymbolAddress((void**)&Qe,  g_Qe);
    cudaGetSymbolAddress((void**)&Ke,  g_Ke);
    cudaGetSymbolAddress((void**)&V,   g_V);
    cudaGetSymbolAddress((void**)&Bm,  g_Bm);
    cudaGetSymbolAddress((void**)&pQ,  g_partQ);
    cudaGetSymbolAddress((void**)&pK,  g_partK);
    cudaGetSymbolAddress((void**)&nrm, g_nrm);

    const long sX = (long)NN * DD;   // batched activation stride
    const long sBm = (long)DD * DD;

    dim3 gProj(DD / 128, NN / 128, BB);     // (4, 32, 8)
    // Projections; Q and K write exp(val/s) directly, V raw.
    gemm128<0, 1><<<gProj, 256>>>(x_q, W_q, b_q, Qe, NN, DD, DD, sX, 0, sX);
    gemm128<0, 1><<<gProj, 256>>>(x_k, W_k, b_k, Ke, NN, DD, DD, sX, 0, sX);
    gemm128<0, 0><<<gProj, 256>>>(x_v, W_v, b_v, V,  NN, DD, DD, sX, 0, sX);

    // Column sums -> combined normalizer 1/(Lq*Lk)
    colsum_part<<<dim3(DD / 256, 8, BB), 256>>>(Qe, pQ);
    colsum_part<<<dim3(DD / 256, 8, BB), 256>>>(Ke, pK);
    colsum_combine<<<dim3(DD / 256, BB), 256>>>();

    // Bm''[d,e] = (sum_n expK[n,d] * V[n,e]) / (Lq[d]*Lk[d])
    dim3 gBm(DD / 128, DD / 128, BB);       // (4, 4, 8)
    gemm128<1, 2><<<gBm, 256>>>(Ke, V, nrm, Bm, DD, DD, NN, sX, sX, sBm);

    // Z = expQ @ Bm''
    dim3 gZ(DD / 128, NN / 128, BB);        // (4, 32, 8)
    gemm128<0, 3><<<gZ, 256>>>(Qe, Bm, nullptr, out, NN, DD, DD, sX, sBm, sX);
}

// round 5
// speedup vs baseline: 2.7553x; 2.7516x over previous
#include <cuda_runtime.h>
#include <math.h>

typedef unsigned int u32; typedef unsigned long long u64;

#define BB 8
#define NSEQ 4096
#define DDIM 512
#define ESCALE 0.2102241038134287f

// ---------------- scratch ----------------
__device__ __align__(1024) float g_WTq[DDIM*DDIM], g_WTk[DDIM*DDIM], g_WTv[DDIM*DDIM];
__device__ __align__(1024) float g_Qe [BB*NSEQ*DDIM];   // exp(Q/s), tf32-rounded, [b][n][d]
__device__ __align__(1024) float g_KT [BB*DDIM*NSEQ];   // exp(K/s)^T, [b][d][n]
__device__ __align__(1024) float g_VT [BB*DDIM*NSEQ];   // V^T, [b][e][n]
__device__ __align__(1024) float g_BmT[BB*DDIM*DDIM];   // (scaled Bm)^T, [b][e][d]
__device__ float g_pQ[BB*16*DDIM], g_Lk[BB*DDIM], g_nrm[BB*DDIM];

// ---------------- helpers ----------------
__device__ __forceinline__ u32 s2u(const void* p) {
    u32 a;
    asm("{ .reg .u64 t; cvta.to.shared.u64 t, %1; cvt.u32.u64 %0, t; }" : "=r"(a) : "l"(p));
    return a;
}
__device__ __forceinline__ u32 tf32r(float f) {
    u32 r; asm("cvt.rna.tf32.f32 %0, %1;" : "=r"(r) : "f"(f)); return r;
}
__device__ __forceinline__ float tf32rf(float f) { return __uint_as_float(tf32r(f)); }
__device__ __forceinline__ void cp16(u32 smem, const void* g) {
    asm volatile("cp.async.cg.shared.global [%0], [%1], 16;" :: "r"(smem), "l"(g));
}
__device__ __forceinline__ void cpcommit() { asm volatile("cp.async.commit_group;" ::: "memory"); }
__device__ __forceinline__ void cpwait1() { asm volatile("cp.async.wait_group 1;" ::: "memory"); }
__device__ __forceinline__ void cpwait0() { asm volatile("cp.async.wait_group 0;" ::: "memory"); }

#define MMA(ac, a, b0, b1)                                                        \
    asm volatile("mma.sync.aligned.m16n8k8.row.col.f32.tf32.tf32.f32 "            \
        "{%0,%1,%2,%3}, {%4,%5,%6,%7}, {%8,%9}, {%0,%1,%2,%3};"                   \
        : "+f"((ac)[0]), "+f"((ac)[1]), "+f"((ac)[2]), "+f"((ac)[3])              \
        : "r"((a)[0]), "r"((a)[1]), "r"((a)[2]), "r"((a)[3]), "r"(b0), "r"(b1))

// ---------------------------------------------------------------------------
// TF32 mma.sync GEMM: C[128 x 128] tile, K-chunk 32, 8 warps (4m x 2n).
// A: [m][k] row-major (lda), B: [n][k] row-major (ldb)  -> C = A * B^T.
// RA=1: A is raw fp32, round fragments to tf32 in-register (B always pre-rounded).
// EPI: 0 Q  (bias+exp, round, row-major out)
//      1 K  (bias+exp, round, transposed out)
//      2 V  (bias, round, transposed out)
//      3 Bm (per-row nrm scale, round, transposed out)
//      4 Z  (plain fp32, row-major out)
// ---------------------------------------------------------------------------
template <int RA, int EPI>
__global__ void __launch_bounds__(256, 1)
gmma(const float* __restrict__ A, const float* __restrict__ Bmat,
     const float* __restrict__ aux, float* __restrict__ outp,
     long sA, long sB, long sO, int lda, int ldb, int ldo, int K)
{
    extern __shared__ float sm[];
    const int tid = threadIdx.x;
    const int w = tid >> 5, lane = tid & 31;
    const int r = lane >> 2, cq = lane & 3;          // groupID, tid-in-group
    const int b = blockIdx.z, m0 = blockIdx.y * 128, n0 = blockIdx.x * 128;
    const int mw = (w & 3) * 32, nw = (w >> 2) * 64;

    const float* pA = A    + (size_t)b * sA + (size_t)m0 * lda;
    const float* pB = Bmat + (size_t)b * sB + (size_t)n0 * ldb;

    float acc[2][8][4];
    #pragma unroll
    for (int mf = 0; mf < 2; mf++)
        #pragma unroll
        for (int nf = 0; nf < 8; nf++)
            #pragma unroll
            for (int e = 0; e < 4; e++) acc[mf][nf][e] = 0.f;

    // SMEM: per stage 9216 floats: A tile [128][36], B tile [128][36]
    auto loadchunk = [&](int c, int s) {
        float* dA = sm + s * 9216;
        float* dB = dA + 4608;
        #pragma unroll
        for (int j = 0; j < 4; j++) {
            int e = tid + j * 256, m = e >> 3, kq = e & 7;
            cp16(s2u(dA + m * 36 + kq * 4), pA + (size_t)m * lda + c * 32 + kq * 4);
        }
        #pragma unroll
        for (int j = 0; j < 4; j++) {
            int e = tid + j * 256, m = e >> 3, kq = e & 7;
            cp16(s2u(dB + m * 36 + kq * 4), pB + (size_t)m * ldb + c * 32 + kq * 4);
        }
        cpcommit();
    };

    auto compute = [&](int s) {
        const float* As = sm + s * 9216;
        const float* Bs = As + 4608;
        #pragma unroll
        for (int ks = 0; ks < 4; ks++) {
            const int kk = ks * 8;
            u32 a[2][4];
            #pragma unroll
            for (int mf = 0; mf < 2; mf++) {
                const float* ap = As + (mw + mf * 16 + r) * 36 + kk + cq;
                float a0 = ap[0], a1 = ap[8 * 36], a2 = ap[4], a3 = ap[8 * 36 + 4];
                if (RA) {
                    a[mf][0] = tf32r(a0); a[mf][1] = tf32r(a1);
                    a[mf][2] = tf32r(a2); a[mf][3] = tf32r(a3);
                } else {
                    a[mf][0] = __float_as_uint(a0); a[mf][1] = __float_as_uint(a1);
                    a[mf][2] = __float_as_uint(a2); a[mf][3] = __float_as_uint(a3);
                }
            }
            #pragma unroll
            for (int nf = 0; nf < 8; nf++) {
                const float* bp = Bs + (nw + nf * 8 + r) * 36 + kk + cq;
                u32 b0 = __float_as_uint(bp[0]);
                u32 b1 = __float_as_uint(bp[4]);
                MMA(acc[0][nf], a[0], b0, b1);
                MMA(acc[1][nf], a[1], b0, b1);
            }
        }
    };

    const int C = K >> 5;
    loadchunk(0, 0);
    if (C > 1) loadchunk(1, 1);
    for (int c = 0; c < C; c++) {
        if (c + 1 < C) cpwait1(); else cpwait0();
        __syncthreads();
        compute(c & 1);
        __syncthreads();
        if (c + 2 < C) loadchunk(c + 2, c & 1);
    }

    // ---------------- epilogue ----------------
    float* sf = sm;   // reuse: 128 x (pitch 132) fp32 = 67584 B
    #pragma unroll
    for (int mf = 0; mf < 2; mf++) {
        #pragma unroll
        for (int nf = 0; nf < 8; nf++) {
            const int mr = mw + mf * 16 + r;
            const int nc = nw + nf * 8 + 2 * cq;
            float v0 = acc[mf][nf][0], v1 = acc[mf][nf][1];
            float v2 = acc[mf][nf][2], v3 = acc[mf][nf][3];
            if constexpr (EPI == 0 || EPI == 1) {
                const float bz0 = aux[n0 + nc], bz1 = aux[n0 + nc + 1];
                v0 = tf32rf(expf((v0 + bz0) * ESCALE));
                v1 = tf32rf(expf((v1 + bz1) * ESCALE));
                v2 = tf32rf(expf((v2 + bz0) * ESCALE));
                v3 = tf32rf(expf((v3 + bz1) * ESCALE));
            } else if constexpr (EPI == 2) {
                const float bz0 = aux[n0 + nc], bz1 = aux[n0 + nc + 1];
                v0 = tf32rf(v0 + bz0); v1 = tf32rf(v1 + bz1);
                v2 = tf32rf(v2 + bz0); v3 = tf32rf(v3 + bz1);
            } else if constexpr (EPI == 3) {
                const float s0 = aux[b * DDIM + m0 + mr];
                const float s8 = aux[b * DDIM + m0 + mr + 8];
                v0 = tf32rf(v0 * s0); v1 = tf32rf(v1 * s0);
                v2 = tf32rf(v2 * s8); v3 = tf32rf(v3 * s8);
            }
            if constexpr (EPI == 0 || EPI == 4) {
                sf[mr * 132 + nc]           = v0;
                sf[mr * 132 + nc + 1]       = v1;
                sf[(mr + 8) * 132 + nc]     = v2;
                sf[(mr + 8) * 132 + nc + 1] = v3;
            } else {
                sf[nc * 132 + mr]           = v0;
                sf[(nc + 1) * 132 + mr]     = v1;
                sf[nc * 132 + mr + 8]       = v2;
                sf[(nc + 1) * 132 + mr + 8] = v3;
            }
        }
    }
    __syncthreads();

    float* po = outp + (size_t)b * sO;
    if constexpr (EPI == 0 || EPI == 4) {
        for (int i = tid; i < 128 * 32; i += 256) {
            int rr = i >> 5, sg = i & 31;
            float4 vv = *(float4*)&sf[rr * 132 + sg * 4];
            *(float4*)(po + (size_t)(m0 + rr) * ldo + n0 + sg * 4) = vv;
        }
    } else {
        for (int i = tid; i < 128 * 32; i += 256) {
            int cc = i >> 5, sg = i & 31;
            float4 vv = *(float4*)&sf[cc * 132 + sg * 4];
            *(float4*)(po + (size_t)(n0 + cc) * ldo + m0 + sg * 4) = vv;
        }
    }
}

// ---------------- small kernels ----------------
__global__ void conv_Wt(const float* __restrict__ W, float* __restrict__ WT)
{
    int i = blockIdx.x * 256 + threadIdx.x;
    int n = i & 511, k = i >> 9;
    WT[(size_t)n * DDIM + k] = tf32rf(W[(size_t)k * DDIM + n]);
}

__global__ void colsumQ(const float* __restrict__ Q, float* __restrict__ part)
{
    const int d = blockIdx.x * 256 + threadIdx.x;
    const int ch = blockIdx.y, b = blockIdx.z;
    const float* p = Q + ((size_t)b * NSEQ + (size_t)ch * 256) * DDIM + d;
    float s0 = 0.f, s1 = 0.f, s2 = 0.f, s3 = 0.f;
    for (int n = 0; n < 256; n += 4) {
        s0 += p[(size_t)(n + 0) * DDIM];
        s1 += p[(size_t)(n + 1) * DDIM];
        s2 += p[(size_t)(n + 2) * DDIM];
        s3 += p[(size_t)(n + 3) * DDIM];
    }
    part[((size_t)b * 16 + ch) * DDIM + d] = (s0 + s1) + (s2 + s3);
}

__global__ void colsumK(const float* __restrict__ KT, float* __restrict__ Lk)
{
    __shared__ float red[128];
    const int d = blockIdx.x, b = blockIdx.y, t = threadIdx.x;
    const float4* p = (const float4*)(KT + ((size_t)b * DDIM + d) * NSEQ);
    float s = 0.f;
    for (int i = t; i < NSEQ / 4; i += 128) {
        float4 v = p[i];
        s += (v.x + v.y) + (v.z + v.w);
    }
    red[t] = s;
    __syncthreads();
    for (int st = 64; st > 0; st >>= 1) {
        if (t < st) red[t] += red[t + st];
        __syncthreads();
    }
    if (t == 0) Lk[(size_t)b * DDIM + d] = red[0];
}

__global__ void combine_nrm(const float* __restrict__ part, const float* __restrict__ Lk,
                            float* __restrict__ nrm)
{
    const int d = blockIdx.x * 256 + threadIdx.x;
    const int b = blockIdx.y;
    float lq = 0.f;
    #pragma unroll
    for (int c = 0; c < 16; c++) lq += part[((size_t)b * 16 + c) * DDIM + d];
    nrm[(size_t)b * DDIM + d] = 1.0f / (lq * Lk[(size_t)b * DDIM + d]);
}

// ---------------- launch ----------------
extern "C" void kernel_launch(void* const* d_in, const int* in_sizes, int n_in,
                              void* d_out, int out_size)
{
    const float* x_q = (const float*)d_in[0];
    const float* x_k = (const float*)d_in[1];
    const float* x_v = (const float*)d_in[2];
    const float* W_q = (const float*)d_in[3];
    const float* b_q = (const float*)d_in[4];
    const float* W_k = (const float*)d_in[5];
    const float* b_k = (const float*)d_in[6];
    const float* W_v = (const float*)d_in[7];
    const float* b_v = (const float*)d_in[8];
    float* out = (float*)d_out;

    float *WTq, *WTk, *WTv, *Qe, *KT, *VT, *BmT, *pQ, *Lk, *nrm;
    cudaGetSymbolAddress((void**)&WTq, g_WTq);
    cudaGetSymbolAddress((void**)&WTk, g_WTk);
    cudaGetSymbolAddress((void**)&WTv, g_WTv);
    cudaGetSymbolAddress((void**)&Qe,  g_Qe);
    cudaGetSymbolAddress((void**)&KT,  g_KT);
    cudaGetSymbolAddress((void**)&VT,  g_VT);
    cudaGetSymbolAddress((void**)&BmT, g_BmT);
    cudaGetSymbolAddress((void**)&pQ,  g_pQ);
    cudaGetSymbolAddress((void**)&Lk,  g_Lk);
    cudaGetSymbolAddress((void**)&nrm, g_nrm);

    const int SM = 73728;
    cudaFuncSetAttribute(gmma<1,0>, cudaFuncAttributeMaxDynamicSharedMemorySize, SM);
    cudaFuncSetAttribute(gmma<1,1>, cudaFuncAttributeMaxDynamicSharedMemorySize, SM);
    cudaFuncSetAttribute(gmma<1,2>, cudaFuncAttributeMaxDynamicSharedMemorySize, SM);
    cudaFuncSetAttribute(gmma<0,3>, cudaFuncAttributeMaxDynamicSharedMemorySize, SM);
    cudaFuncSetAttribute(gmma<0,4>, cudaFuncAttributeMaxDynamicSharedMemorySize, SM);

    const long sX  = (long)NSEQ * DDIM;
    const long sT  = (long)DDIM * NSEQ;
    const long sBm = (long)DDIM * DDIM;

    conv_Wt<<<1024, 256>>>(W_q, WTq);
    conv_Wt<<<1024, 256>>>(W_k, WTk);
    conv_Wt<<<1024, 256>>>(W_v, WTv);

    dim3 gp(4, 32, 8);
    // Projections: Q row-major exp; K,V transposed outputs.
    gmma<1,0><<<gp, 256, SM>>>(x_q, WTq, b_q, Qe, sX, 0, sX, DDIM, DDIM, DDIM, DDIM);
    gmma<1,1><<<gp, 256, SM>>>(x_k, WTk, b_k, KT, sX, 0, sT, DDIM, DDIM, NSEQ, DDIM);
    gmma<1,2><<<gp, 256, SM>>>(x_v, WTv, b_v, VT, sX, 0, sT, DDIM, DDIM, NSEQ, DDIM);

    colsumQ<<<dim3(2, 16, 8), 256>>>(Qe, pQ);
    colsumK<<<dim3(512, 8), 128>>>(KT, Lk);
    combine_nrm<<<dim3(2, 8), 256>>>(pQ, Lk, nrm);

    // Bm^T = ((KT * VT^T) scaled by nrm rows)^T
    dim3 gb(4, 4, 8);
    gmma<0,3><<<gb, 256, SM>>>(KT, VT, nrm, BmT, sT, sT, sBm, NSEQ, NSEQ, DDIM, NSEQ);

    // Z = Qe * BmT^T
    dim3 gz(4, 32, 8);
    gmma<0,4><<<gz, 256, SM>>>(Qe, BmT, nullptr, out, sX, sBm, sX, DDIM, DDIM, DDIM, DDIM);
}